// round 1
// baseline (speedup 1.0000x reference)
#include <cuda_runtime.h>
#include <math.h>

// Shapes (fixed by the problem)
#define B_ 8
#define N_ 3
#define C_ 64
#define F_ 128
#define H_ 128
#define W_ 128
#define h_ 64
#define w_ 64

// Scratch (device globals -- no allocation allowed)
__device__ float g_A[C_ * F_];          // Wc^T * Wf  [c][f]
__device__ float g_tvec[C_];            // Wc^T * bf
__device__ float g_Qt[B_ * C_ * h_ * w_];   // qt at low res
__device__ float g_Val[B_ * C_ * h_ * w_];  // values at low res
__device__ float g_Lm[B_ * h_ * w_];        // mainstream-key logit

// ---------------------------------------------------------------------------
// Kernel 0: tiny precompute of A = Wc^T Wf and tvec = Wc^T bf
// ---------------------------------------------------------------------------
__global__ void k0_precompute(const float* __restrict__ Wc,
                              const float* __restrict__ Wf,
                              const float* __restrict__ bf) {
    int i = blockIdx.x * blockDim.x + threadIdx.x;
    if (i < C_ * F_) {
        int c = i >> 7, f = i & 127;
        float a = 0.f;
#pragma unroll 8
        for (int d = 0; d < C_; d++) a += Wc[d * C_ + c] * Wf[d * F_ + f];
        g_A[i] = a;
    }
    if (i < C_) {
        float t = 0.f;
        for (int d = 0; d < C_; d++) t += Wc[d * C_ + i] * bf[d];
        g_tvec[i] = t;
    }
}

// ---------------------------------------------------------------------------
// Kernel 1: low-res dense math. Per low-res pixel:
//   qt[c]   = sum_f A[c,f] m[f] + tvec[c]
//   keys[c] = sum_f Wk[c,f] m[f] + bk[c]     (only needed for Lm)
//   val[c]  = 3x3 conv(m, Vw)[c] + Vb[c]
//   Lm      = sum_c keys[c]*qt[c]
// Block: 8x8 pixel tile of one batch. 256 threads = 64 c x 4 pixel-groups,
// each group owns 2 rows x 8 cols. Weights staged in SMEM per f-chunk of 8.
// ---------------------------------------------------------------------------
#define SM_MT 0        // [8 f][10][10] = 800 floats
#define SM_WA 800      // [8 f][64 c]   = 512
#define SM_WK 1312     // 512
#define SM_WV 1824     // [8 f][64 c][9] = 4608
#define SM_RED 6432    // 128
#define SM_TOT 6560
#define SM_STAGE 0     // reuse (needs 64*65=4160 <= 6432)

__global__ __launch_bounds__(256, 2) void k1_lowres(
    const float* __restrict__ ms,   // [B,128,64,64]
    const float* __restrict__ Wk,   // [64,128]
    const float* __restrict__ bk,   // [64]
    const float* __restrict__ Vw,   // [64,128,3,3]
    const float* __restrict__ Vb)   // [64]
{
    __shared__ float sm[SM_TOT];

    const int tid = threadIdx.x;
    const int b = blockIdx.z;
    const int gx0 = blockIdx.x * 8, gy0 = blockIdx.y * 8;
    const int c = tid & 63, pg = tid >> 6;   // pg rows: 2pg, 2pg+1

    float q0[8] = {0}, q1[8] = {0};
    float k0a[8] = {0}, k1a[8] = {0};
    float v0[8] = {0}, v1[8] = {0};

    for (int chunk = 0; chunk < 16; chunk++) {
        const int f0 = chunk * 8;
        __syncthreads();
        // stage mainstream tile chunk (with halo, zero-padded SAME)
        for (int i = tid; i < 800; i += 256) {
            int fc = i / 100;
            int rr = (i / 10) % 10;
            int cc = i % 10;
            int gy = gy0 + rr - 1, gx = gx0 + cc - 1;
            float v = 0.f;
            if (gy >= 0 && gy < h_ && gx >= 0 && gx < w_)
                v = ms[((b * F_ + f0 + fc) * h_ + gy) * w_ + gx];
            sm[SM_MT + i] = v;
        }
        // stage weights chunk (coalesced)
        for (int i = tid; i < 512; i += 256) {
            int cc2 = i >> 3, fc = i & 7;
            sm[SM_WA + fc * 64 + cc2] = g_A[cc2 * F_ + f0 + fc];
            sm[SM_WK + fc * 64 + cc2] = Wk[cc2 * F_ + f0 + fc];
        }
        for (int i = tid; i < 4608; i += 256) {
            int cc2 = i / 72;
            int r = i % 72;
            int fc = r / 9, j = r % 9;
            sm[SM_WV + (fc * 64 + cc2) * 9 + j] = Vw[(cc2 * F_ + f0 + fc) * 9 + j];
        }
        __syncthreads();

#pragma unroll 2
        for (int fc = 0; fc < 8; fc++) {
            float a = sm[SM_WA + fc * 64 + c];
            float wk = sm[SM_WK + fc * 64 + c];
            float vw[9];
#pragma unroll
            for (int j = 0; j < 9; j++) vw[j] = sm[SM_WV + (fc * 64 + c) * 9 + j];
            const float* mrow = sm + SM_MT + fc * 100 + (2 * pg) * 10;
            float w0[10], w1[10], w2[10], w3[10];
#pragma unroll
            for (int cc2 = 0; cc2 < 10; cc2++) {
                w0[cc2] = mrow[cc2];
                w1[cc2] = mrow[10 + cc2];
                w2[cc2] = mrow[20 + cc2];
                w3[cc2] = mrow[30 + cc2];
            }
#pragma unroll
            for (int x = 0; x < 8; x++) {
                float m0 = w1[x + 1], m1 = w2[x + 1];
                q0[x] = fmaf(a, m0, q0[x]);
                k0a[x] = fmaf(wk, m0, k0a[x]);
                q1[x] = fmaf(a, m1, q1[x]);
                k1a[x] = fmaf(wk, m1, k1a[x]);
                float s0 = v0[x];
                s0 = fmaf(vw[0], w0[x], s0);
                s0 = fmaf(vw[1], w0[x + 1], s0);
                s0 = fmaf(vw[2], w0[x + 2], s0);
                s0 = fmaf(vw[3], w1[x], s0);
                s0 = fmaf(vw[4], w1[x + 1], s0);
                s0 = fmaf(vw[5], w1[x + 2], s0);
                s0 = fmaf(vw[6], w2[x], s0);
                s0 = fmaf(vw[7], w2[x + 1], s0);
                s0 = fmaf(vw[8], w2[x + 2], s0);
                v0[x] = s0;
                float s1 = v1[x];
                s1 = fmaf(vw[0], w1[x], s1);
                s1 = fmaf(vw[1], w1[x + 1], s1);
                s1 = fmaf(vw[2], w1[x + 2], s1);
                s1 = fmaf(vw[3], w2[x], s1);
                s1 = fmaf(vw[4], w2[x + 1], s1);
                s1 = fmaf(vw[5], w2[x + 2], s1);
                s1 = fmaf(vw[6], w3[x], s1);
                s1 = fmaf(vw[7], w3[x + 1], s1);
                s1 = fmaf(vw[8], w3[x + 2], s1);
                v1[x] = s1;
            }
        }
    }

    // epilogue
    const float tq = g_tvec[c], tb = bk[c], tv = Vb[c];

    // Lm partials: keys*qt summed over c (warp covers 32 distinct c, same pg)
    float lm[16];
#pragma unroll
    for (int x = 0; x < 8; x++) {
        lm[x] = (k0a[x] + tb) * (q0[x] + tq);
        lm[8 + x] = (k1a[x] + tb) * (q1[x] + tq);
    }
#pragma unroll
    for (int off = 16; off; off >>= 1) {
#pragma unroll
        for (int p = 0; p < 16; p++)
            lm[p] += __shfl_down_sync(0xffffffffu, lm[p], off);
    }

    __syncthreads();  // compute done; safe to reuse SMEM as stage
    const int warp = tid >> 5, lane = tid & 31;
    if (lane == 0) {
#pragma unroll
        for (int p = 0; p < 16; p++) sm[SM_RED + warp * 16 + p] = lm[p];
    }
    // stage qt for coalesced transpose-store (pad 65 kills bank conflicts)
#pragma unroll
    for (int x = 0; x < 8; x++) {
        sm[SM_STAGE + c * 65 + pg * 16 + x] = q0[x] + tq;
        sm[SM_STAGE + c * 65 + pg * 16 + 8 + x] = q1[x] + tq;
    }
    __syncthreads();
    if (tid < 64) {
        int pg2 = tid >> 4, p = tid & 15;
        float L = sm[SM_RED + (2 * pg2) * 16 + p] + sm[SM_RED + (2 * pg2 + 1) * 16 + p];
        g_Lm[(b * h_ + gy0 + 2 * pg2 + (p >> 3)) * w_ + gx0 + (p & 7)] = L;
    }
#pragma unroll
    for (int j = 0; j < 16; j++) {
        int i = j * 256 + tid;
        int c2 = i >> 6, p = i & 63;
        g_Qt[((b * C_ + c2) * h_ + gy0 + (p >> 3)) * w_ + gx0 + (p & 7)] =
            sm[SM_STAGE + c2 * 65 + p];
    }
    __syncthreads();
#pragma unroll
    for (int x = 0; x < 8; x++) {
        sm[SM_STAGE + c * 65 + pg * 16 + x] = v0[x] + tv;
        sm[SM_STAGE + c * 65 + pg * 16 + 8 + x] = v1[x] + tv;
    }
    __syncthreads();
#pragma unroll
    for (int j = 0; j < 16; j++) {
        int i = j * 256 + tid;
        int c2 = i >> 6, p = i & 63;
        g_Val[((b * C_ + c2) * h_ + gy0 + (p >> 3)) * w_ + gx0 + (p & 7)] =
            sm[SM_STAGE + c2 * 65 + p];
    }
}

// ---------------------------------------------------------------------------
// Kernel 2: high-res attention. One thread per output pixel.
// Pass 1: logits over contexts (dot with qt).  Softmax over 4.
// Pass 2: weighted sum (contexts re-read from L2).
// ---------------------------------------------------------------------------
__global__ __launch_bounds__(256) void k2_highres(const float* __restrict__ ctx,
                                                  float* __restrict__ out) {
    int idx = blockIdx.x * 256 + threadIdx.x;
    int b = idx >> 14;
    int hw = idx & 16383;
    int h = hw >> 7, w = hw & 127;
    int y = h >> 1, x = w >> 1;

    const float* qt = g_Qt + ((b * C_) * h_ + y) * w_ + x;   // stride 4096 per c
    const float* cp = ctx + (size_t)b * N_ * C_ * (H_ * W_) + hw;  // stride 16384 per (n,c)

    float l0 = 0.f, l1 = 0.f, l2 = 0.f;
#pragma unroll 4
    for (int c = 0; c < C_; c++) {
        float q = qt[c * 4096];
        l0 = fmaf(cp[c * 16384], q, l0);
        l1 = fmaf(cp[(64 + c) * 16384], q, l1);
        l2 = fmaf(cp[(128 + c) * 16384], q, l2);
    }
    float l3 = g_Lm[(b * h_ + y) * w_ + x];

    float mx = fmaxf(fmaxf(l0, l1), fmaxf(l2, l3));
    float e0 = __expf(l0 - mx), e1 = __expf(l1 - mx);
    float e2 = __expf(l2 - mx), e3 = __expf(l3 - mx);
    float inv = 1.f / (e0 + e1 + e2 + e3);
    e0 *= inv; e1 *= inv; e2 *= inv; e3 *= inv;

    const float* vp = g_Val + ((b * C_) * h_ + y) * w_ + x;
    float* op = out + (size_t)b * C_ * (H_ * W_) + hw;
#pragma unroll 4
    for (int c = 0; c < C_; c++) {
        float o = e3 * vp[c * 4096];
        o = fmaf(e0, cp[c * 16384], o);
        o = fmaf(e1, cp[(64 + c) * 16384], o);
        o = fmaf(e2, cp[(128 + c) * 16384], o);
        op[c * 16384] = o;
    }
}

// ---------------------------------------------------------------------------
extern "C" void kernel_launch(void* const* d_in, const int* in_sizes, int n_in,
                              void* d_out, int out_size) {
    (void)in_sizes; (void)n_in; (void)out_size;
    const float* contexts = (const float*)d_in[0];
    const float* mainstream = (const float*)d_in[1];
    const float* Wc = (const float*)d_in[2];
    // d_in[3] = bc : cancels in softmax, unused
    const float* Wf = (const float*)d_in[4];
    const float* bf = (const float*)d_in[5];
    const float* Wk = (const float*)d_in[6];
    const float* bk = (const float*)d_in[7];
    const float* Vw = (const float*)d_in[8];
    const float* Vb = (const float*)d_in[9];
    float* out = (float*)d_out;

    k0_precompute<<<32, 256>>>(Wc, Wf, bf);
    dim3 g1(8, 8, 8);
    k1_lowres<<<g1, 256>>>(mainstream, Wk, bk, Vw, Vb);
    k2_highres<<<512, 256>>>(contexts, out);
}